// round 14
// baseline (speedup 1.0000x reference)
#include <cuda_runtime.h>

#define N_NODES 100000
#define E_MAX   3200000
#define F_INN   300
#define HID     16
#define C_OUT   10
#define H2P     12
#define NBLK_SCAN 98   // ceil(100000/1024)
#define XS_STR  33     // xs stride: 33 % 32 == 1 -> conflict-free LDS
#define DEG_MASK 0xFFFFFFFFFFULL   // low 40 bits: weighted degree, 2^-24 fixed point

// ---------------- device scratch (static, no allocation) ----------------
// g_hist zero at load; k_scan re-zeroes after reading. g_arrive/g_flag reset
// by k_reorder (which runs strictly after k_scan) -> clean on every replay.
__device__ unsigned long long g_hist[N_NODES];  // count<<40 | fixedpoint(deg)
__device__ __align__(16) float g_dinv[N_NODES];
__device__ int   g_start[N_NODES + 1];
__device__ int   g_pos[N_NODES];
__device__ int   g_bsum[NBLK_SCAN];
__device__ int   g_boff[NBLK_SCAN];
__device__ int   g_arrive, g_flag;
__device__ __align__(16) int2  g_edge[E_MAX];   // {row, raw-weight-bits}, sorted by col
__device__ __align__(16) float g_h1[N_NODES * HID];   // dinv-scaled h1
__device__ __align__(16) float g_h2[N_NODES * H2P];   // dinv-scaled h2

#define FFMA2(acc, a, b) \
    asm("fma.rn.f32x2 %0, %1, %2, %0;" : "+l"(acc) : "l"(a), "l"(b))

// per-block int64-vs-int32 detect (warp 0 ballot -> shared flag).
__device__ __forceinline__ int detect_is64(const void* ei, int* sh) {
    if (threadIdx.x < 32) {
        const long long* p = (const long long*)ei;
        long long v = p[threadIdx.x];
        unsigned m = __ballot_sync(0xffffffffu, v >= 0 && v < N_NODES);
        if (threadIdx.x == 0) *sh = (m == 0xffffffffu);
    }
    __syncthreads();
    return *sh;
}

__device__ __forceinline__ unsigned long long histpack(float w) {
    return (1ULL << 40) | __float2ull_rn(w * 16777216.0f);
}

// ---------------- kernels ----------------
// histogram: 2 edges per thread, vectorized index/weight loads
__global__ void k_prep(const void* __restrict__ eiv,
                       const float* __restrict__ ew, int E) {
    __shared__ int s64;
    int is64 = detect_is64(eiv, &s64);
    int e = (blockIdx.x * blockDim.x + threadIdx.x) * 2;
    if (e >= E) return;
    if (e + 1 < E) {
        int c0, c1;
        if (is64) {
            longlong2 cc = *(const longlong2*)&((const long long*)eiv)[E + e];
            c0 = (int)cc.x; c1 = (int)cc.y;
        } else {
            int2 cc = *(const int2*)&((const int*)eiv)[E + e];
            c0 = cc.x; c1 = cc.y;
        }
        float2 ww = *(const float2*)&ew[e];
        atomicAdd(&g_hist[c0], histpack(ww.x));
        atomicAdd(&g_hist[c1], histpack(ww.y));
    } else {
        int c = is64 ? (int)((const long long*)eiv)[E + e]
                     : ((const int*)eiv)[E + e];
        atomicAdd(&g_hist[c], histpack(ew[e]));
    }
}

// single-kernel scan: block-local exclusive scan + dinv + hist reset,
// then last-arriving block scans the 98 block sums and releases the rest.
__global__ void __launch_bounds__(1024) k_scan(int E) {
    __shared__ int wsum[32];
    int i = blockIdx.x * 1024 + threadIdx.x;
    int lane = threadIdx.x & 31, wid = threadIdx.x >> 5;
    int v = 0;
    if (i < N_NODES) {
        unsigned long long hv = g_hist[i];
        g_hist[i] = 0ULL;   // reset for the next call / replay
        v = (int)(hv >> 40);
        float deg = (float)((double)(hv & DEG_MASK) * (1.0 / 16777216.0));
        g_dinv[i] = rsqrtf(deg + 1.0f);   // +1 = self loop weight
    }
    int incl = v;
#pragma unroll
    for (int d = 1; d < 32; d <<= 1) {
        int t = __shfl_up_sync(0xffffffffu, incl, d);
        if (lane >= d) incl += t;
    }
    if (lane == 31) wsum[wid] = incl;
    __syncthreads();
    if (wid == 0) {
        int s = wsum[lane];
#pragma unroll
        for (int d = 1; d < 32; d <<= 1) {
            int t = __shfl_up_sync(0xffffffffu, s, d);
            if (lane >= d) s += t;
        }
        wsum[lane] = s;
    }
    __syncthreads();
    int woff = (wid > 0) ? wsum[wid - 1] : 0;
    int locex = incl - v + woff;       // block-local exclusive prefix
    int btotal = wsum[31];

    if (threadIdx.x == 0) {
        g_bsum[blockIdx.x] = btotal;
        __threadfence();
    }
    if (wid == 0) {
        int rank = 0;
        if (lane == 0) rank = atomicAdd(&g_arrive, 1);
        rank = __shfl_sync(0xffffffffu, rank, 0);
        if (rank == NBLK_SCAN - 1) {
            // last block: warp-scan the 98 block sums (4 per lane)
            int e0 = (4 * lane + 0 < NBLK_SCAN) ? __ldcg(&g_bsum[4 * lane + 0]) : 0;
            int e1 = (4 * lane + 1 < NBLK_SCAN) ? __ldcg(&g_bsum[4 * lane + 1]) : 0;
            int e2 = (4 * lane + 2 < NBLK_SCAN) ? __ldcg(&g_bsum[4 * lane + 2]) : 0;
            int e3 = (4 * lane + 3 < NBLK_SCAN) ? __ldcg(&g_bsum[4 * lane + 3]) : 0;
            int s4 = e0 + e1 + e2 + e3;
            int inc4 = s4;
#pragma unroll
            for (int d = 1; d < 32; d <<= 1) {
                int t = __shfl_up_sync(0xffffffffu, inc4, d);
                if (lane >= d) inc4 += t;
            }
            int base = inc4 - s4;
            if (4 * lane + 0 < NBLK_SCAN) g_boff[4 * lane + 0] = base;
            if (4 * lane + 1 < NBLK_SCAN) g_boff[4 * lane + 1] = base + e0;
            if (4 * lane + 2 < NBLK_SCAN) g_boff[4 * lane + 2] = base + e0 + e1;
            if (4 * lane + 3 < NBLK_SCAN) g_boff[4 * lane + 3] = base + e0 + e1 + e2;
            __threadfence();
            if (lane == 0) atomicExch(&g_flag, 1);
        } else {
            if (lane == 0)
                while (atomicAdd(&g_flag, 0) == 0) __nanosleep(64);
        }
    }
    __syncthreads();
    int boff = __ldcg(&g_boff[blockIdx.x]);
    if (i < N_NODES) {
        int s = locex + boff;
        g_start[i] = s;
        g_pos[i] = s;
    }
    if (i == 0) g_start[N_NODES] = E;
}

// scatter edges into CSR order ({row, raw weight}); 2 edges per thread.
// Also resets the scan kernel's arrive/flag state for the next replay.
__global__ void k_reorder(const void* __restrict__ eiv,
                          const float* __restrict__ ew, int E) {
    __shared__ int s64;
    if (blockIdx.x == 0 && threadIdx.x == 0) { g_arrive = 0; g_flag = 0; }
    int is64 = detect_is64(eiv, &s64);
    int e = (blockIdx.x * blockDim.x + threadIdx.x) * 2;
    if (e >= E) return;
    if (e + 1 < E) {
        int r0, c0, r1, c1;
        if (is64) {
            const long long* ei = (const long long*)eiv;
            longlong2 rr = *(const longlong2*)&ei[e];
            longlong2 cc = *(const longlong2*)&ei[E + e];
            r0 = (int)rr.x; r1 = (int)rr.y;
            c0 = (int)cc.x; c1 = (int)cc.y;
        } else {
            const int* ei = (const int*)eiv;
            int2 rr = *(const int2*)&ei[e];
            int2 cc = *(const int2*)&ei[E + e];
            r0 = rr.x; r1 = rr.y;
            c0 = cc.x; c1 = cc.y;
        }
        float2 ww = *(const float2*)&ew[e];
        int p0 = atomicAdd(&g_pos[c0], 1);
        int p1 = atomicAdd(&g_pos[c1], 1);
        g_edge[p0] = make_int2(r0, __float_as_int(ww.x));
        g_edge[p1] = make_int2(r1, __float_as_int(ww.y));
    } else {
        int r, c;
        if (is64) {
            const long long* ei = (const long long*)eiv;
            r = (int)ei[e]; c = (int)ei[E + e];
        } else {
            const int* ei = (const int*)eiv;
            r = ei[e]; c = ei[E + e];
        }
        int p = atomicAdd(&g_pos[c], 1);
        g_edge[p] = make_int2(r, __float_as_int(ew[e]));
    }
}

// h1s = (x @ W1) * dinv  (dinv-scaled features)
__global__ void __launch_bounds__(128) k_gemm1(const float* __restrict__ x,
                                               const float* __restrict__ W1) {
    __shared__ __align__(16) float w1s[F_INN * HID];   // 19200 B
    __shared__ float xs[128 * XS_STR];                 // 16896 B
    int tid = threadIdx.x;
    for (int i = tid; i < F_INN * HID; i += 128) w1s[i] = W1[i];
    int node0 = blockIdx.x * 128;

    unsigned long long acc[8];
#pragma unroll
    for (int j = 0; j < 8; j++) acc[j] = 0ULL;

    for (int kc = 0; kc < F_INN; kc += 32) {
        int chunk = min(32, F_INN - kc);
        int cq = chunk >> 2;  // float4s per node: 8 or 3
        __syncthreads();
        for (int idx = tid; idx < 128 * cq; idx += 128) {
            int nd = idx / cq, q = idx - nd * cq;
            float4 v = make_float4(0.f, 0.f, 0.f, 0.f);
            if (node0 + nd < N_NODES)
                v = *(const float4*)&x[(node0 + nd) * F_INN + kc + q * 4];
            float* dst = &xs[nd * XS_STR + q * 4];
            dst[0] = v.x; dst[1] = v.y; dst[2] = v.z; dst[3] = v.w;
        }
        __syncthreads();

        for (int k = 0; k < chunk; k++) {
            float xv = xs[tid * XS_STR + k];
            unsigned long long xx;
            asm("mov.b64 %0, {%1, %1};" : "=l"(xx) : "f"(xv));
            const ulonglong2* wr = (const ulonglong2*)&w1s[(kc + k) * HID];
            ulonglong2 w0 = wr[0], w1 = wr[1], w2 = wr[2], w3 = wr[3];
            FFMA2(acc[0], xx, w0.x); FFMA2(acc[1], xx, w0.y);
            FFMA2(acc[2], xx, w1.x); FFMA2(acc[3], xx, w1.y);
            FFMA2(acc[4], xx, w2.x); FFMA2(acc[5], xx, w2.y);
            FFMA2(acc[6], xx, w3.x); FFMA2(acc[7], xx, w3.y);
        }
    }

    int node = node0 + tid;
    if (node < N_NODES) {
        float di = g_dinv[node];
        float o[16];
#pragma unroll
        for (int j = 0; j < 8; j++)
            asm("mov.b64 {%0, %1}, %2;" : "=f"(o[2 * j]), "=f"(o[2 * j + 1]) : "l"(acc[j]));
#pragma unroll
        for (int j = 0; j < 16; j++) o[j] *= di;
        float4* dst = (float4*)&g_h1[node * HID];
        dst[0] = make_float4(o[0], o[1], o[2], o[3]);
        dst[1] = make_float4(o[4], o[5], o[6], o[7]);
        dst[2] = make_float4(o[8], o[9], o[10], o[11]);
        dst[3] = make_float4(o[12], o[13], o[14], o[15]);
    }
}

// conv1 + node1 fused: warp per node gather (x2 ILP), then
// v = relu(di*(acc + h1s_self) + b1); h2s = (W2 @ v) * di
__global__ void __launch_bounds__(256) k_conv1(const float* __restrict__ b1,
                                               const float* __restrict__ W2) {
    int warp = (blockIdx.x * blockDim.x + threadIdx.x) >> 5;
    if (warp >= N_NODES) return;
    int lane = threadIdx.x & 31;
    int q = lane & 3, eg = lane >> 2;
    int s = g_start[warp], e = g_start[warp + 1];
    float4 acc0 = make_float4(0.f, 0.f, 0.f, 0.f);
    float4 acc1 = make_float4(0.f, 0.f, 0.f, 0.f);
    int idx = s + eg;
    for (; idx + 8 < e; idx += 16) {
        int2 e0 = g_edge[idx];
        int2 e1 = g_edge[idx + 8];
        float n0 = __int_as_float(e0.y);
        float n1 = __int_as_float(e1.y);
        float4 h0 = *(const float4*)&g_h1[e0.x * HID + q * 4];
        float4 h1 = *(const float4*)&g_h1[e1.x * HID + q * 4];
        acc0.x += h0.x * n0; acc0.y += h0.y * n0;
        acc0.z += h0.z * n0; acc0.w += h0.w * n0;
        acc1.x += h1.x * n1; acc1.y += h1.y * n1;
        acc1.z += h1.z * n1; acc1.w += h1.w * n1;
    }
    if (idx < e) {
        int2 e0 = g_edge[idx];
        float n0 = __int_as_float(e0.y);
        float4 h0 = *(const float4*)&g_h1[e0.x * HID + q * 4];
        acc0.x += h0.x * n0; acc0.y += h0.y * n0;
        acc0.z += h0.z * n0; acc0.w += h0.w * n0;
    }
    float4 acc = make_float4(acc0.x + acc1.x, acc0.y + acc1.y,
                             acc0.z + acc1.z, acc0.w + acc1.w);
#pragma unroll
    for (int d = 4; d < 32; d <<= 1) {
        acc.x += __shfl_xor_sync(0xffffffffu, acc.x, d);
        acc.y += __shfl_xor_sync(0xffffffffu, acc.y, d);
        acc.z += __shfl_xor_sync(0xffffffffu, acc.z, d);
        acc.w += __shfl_xor_sync(0xffffffffu, acc.w, d);
    }
    float di = g_dinv[warp];
    float4 h1q = *(const float4*)&g_h1[warp * HID + q * 4];   // dinv-scaled
    float4 bq  = *(const float4*)&b1[q * 4];
    float4 v;
    v.x = fmaxf((acc.x + h1q.x) * di + bq.x, 0.f);
    v.y = fmaxf((acc.y + h1q.y) * di + bq.y, 0.f);
    v.z = fmaxf((acc.z + h1q.z) * di + bq.z, 0.f);
    v.w = fmaxf((acc.w + h1q.w) * di + bq.w, 0.f);
    float vv[16];
#pragma unroll
    for (int c = 0; c < 4; c++) {
        vv[4 * c + 0] = __shfl_sync(0xffffffffu, v.x, c);
        vv[4 * c + 1] = __shfl_sync(0xffffffffu, v.y, c);
        vv[4 * c + 2] = __shfl_sync(0xffffffffu, v.z, c);
        vv[4 * c + 3] = __shfl_sync(0xffffffffu, v.w, c);
    }
    if (lane < H2P) {
        float o = 0.f;
        if (lane < C_OUT) {
#pragma unroll
            for (int k = 0; k < HID; k++)
                o += vv[k] * __ldg(&W2[k * C_OUT + lane]);
            o *= di;   // dinv-scaled h2
        }
        g_h2[warp * H2P + lane] = o;
    }
}

// conv2 + final fused: gather (x2 ILP), t = di*(acc + h2s_self) + b2, log_softmax
__global__ void __launch_bounds__(256) k_conv2(const float* __restrict__ b2,
                                               float* __restrict__ out) {
    int warp = (blockIdx.x * blockDim.x + threadIdx.x) >> 5;
    if (warp >= N_NODES) return;
    int lane = threadIdx.x & 31;
    int q = lane & 3, eg = lane >> 2;
    int s = g_start[warp], e = g_start[warp + 1];
    float4 acc0 = make_float4(0.f, 0.f, 0.f, 0.f);
    float4 acc1 = make_float4(0.f, 0.f, 0.f, 0.f);
    int idx = s + eg;
    for (; idx + 8 < e; idx += 16) {
        int2 e0 = g_edge[idx];
        int2 e1 = g_edge[idx + 8];
        float n0 = __int_as_float(e0.y);
        float n1 = __int_as_float(e1.y);
        if (q < 3) {
            float4 h0 = *(const float4*)&g_h2[e0.x * H2P + q * 4];
            float4 h1 = *(const float4*)&g_h2[e1.x * H2P + q * 4];
            acc0.x += h0.x * n0; acc0.y += h0.y * n0;
            acc0.z += h0.z * n0; acc0.w += h0.w * n0;
            acc1.x += h1.x * n1; acc1.y += h1.y * n1;
            acc1.z += h1.z * n1; acc1.w += h1.w * n1;
        }
    }
    if (idx < e) {
        int2 e0 = g_edge[idx];
        float n0 = __int_as_float(e0.y);
        if (q < 3) {
            float4 h0 = *(const float4*)&g_h2[e0.x * H2P + q * 4];
            acc0.x += h0.x * n0; acc0.y += h0.y * n0;
            acc0.z += h0.z * n0; acc0.w += h0.w * n0;
        }
    }
    float4 acc = make_float4(acc0.x + acc1.x, acc0.y + acc1.y,
                             acc0.z + acc1.z, acc0.w + acc1.w);
#pragma unroll
    for (int d = 4; d < 32; d <<= 1) {
        acc.x += __shfl_xor_sync(0xffffffffu, acc.x, d);
        acc.y += __shfl_xor_sync(0xffffffffu, acc.y, d);
        acc.z += __shfl_xor_sync(0xffffffffu, acc.z, d);
        acc.w += __shfl_xor_sync(0xffffffffu, acc.w, d);
    }
    float di = g_dinv[warp];
    float4 tq = make_float4(0.f, 0.f, 0.f, 0.f);
    if (q < 3) {
        float4 h2q = *(const float4*)&g_h2[warp * H2P + q * 4];  // dinv-scaled
        tq.x = (acc.x + h2q.x) * di;
        tq.y = (acc.y + h2q.y) * di;
        tq.z = (acc.z + h2q.z) * di;
        tq.w = (acc.w + h2q.w) * di;
    }
    int src = lane >> 2;
    float a0 = __shfl_sync(0xffffffffu, tq.x, src);
    float a1 = __shfl_sync(0xffffffffu, tq.y, src);
    float a2 = __shfl_sync(0xffffffffu, tq.z, src);
    float a3 = __shfl_sync(0xffffffffu, tq.w, src);
    float tj = (q == 0) ? a0 : (q == 1) ? a1 : (q == 2) ? a2 : a3;
    tj = (lane < C_OUT) ? tj + __ldg(&b2[lane]) : -3.4e38f;
    float m = tj;
#pragma unroll
    for (int d = 16; d >= 1; d >>= 1) m = fmaxf(m, __shfl_xor_sync(0xffffffffu, m, d));
    float ex = (lane < C_OUT) ? expf(tj - m) : 0.f;
    float ssum = ex;
#pragma unroll
    for (int d = 16; d >= 1; d >>= 1) ssum += __shfl_xor_sync(0xffffffffu, ssum, d);
    float l = logf(ssum) + m;
    if (lane < C_OUT) out[warp * C_OUT + lane] = tj - l;
}

// ---------------- launcher ----------------
extern "C" void kernel_launch(void* const* d_in, const int* in_sizes, int n_in,
                              void* d_out, int out_size) {
    const float* x  = (const float*)d_in[0];
    const void*  ei = d_in[1];
    const float* ew = (const float*)d_in[2];
    const float* W1 = (const float*)d_in[3];
    const float* b1 = (const float*)d_in[4];
    const float* W2 = (const float*)d_in[5];
    const float* b2 = (const float*)d_in[6];
    float* out = (float*)d_out;
    int E = in_sizes[2];

    int half = (E + 1) / 2;
    k_prep<<<(half + 255) / 256, 256>>>(ei, ew, E);
    k_scan<<<NBLK_SCAN, 1024>>>(E);
    k_reorder<<<(half + 255) / 256, 256>>>(ei, ew, E);
    k_gemm1<<<(N_NODES + 127) / 128, 128>>>(x, W1);
    k_conv1<<<(N_NODES * 32 + 255) / 256, 256>>>(b1, W2);
    k_conv2<<<(N_NODES * 32 + 255) / 256, 256>>>(b2, out);
}

// round 15
// speedup vs baseline: 1.1329x; 1.1329x over previous
#include <cuda_runtime.h>

#define N_NODES 100000
#define E_MAX   3200000
#define F_INN   300
#define HID     16
#define C_OUT   10
#define H2P     12
#define NBLK_SCAN 98   // ceil(100000/1024)
#define XS_STR  33     // xs stride: 33 % 32 == 1 -> conflict-free LDS
#define NCHUNK  9      // 9 full 32-wide k-chunks; tail of 12
#define DEG_MASK 0xFFFFFFFFFFULL   // low 40 bits: weighted degree, 2^-24 fixed point

// ---------------- device scratch (static, no allocation) ----------------
// g_hist is zero at module load and re-zeroed by k_scanA after each read,
// so every kernel_launch call (and graph replay) sees a clean histogram.
__device__ unsigned long long g_hist[N_NODES];  // count<<40 | fixedpoint(deg)
__device__ __align__(16) float g_dinv[N_NODES];
__device__ int   g_start[N_NODES + 1];
__device__ int   g_pos[N_NODES];
__device__ int   g_bsum[NBLK_SCAN];
__device__ __align__(16) int2  g_edge[E_MAX];   // {row, raw-weight-bits}, sorted by col
__device__ __align__(16) float g_h1[N_NODES * HID];   // dinv-scaled h1
__device__ __align__(16) float g_h2[N_NODES * H2P];   // dinv-scaled h2

#define FFMA2(acc, a, b) \
    asm("fma.rn.f32x2 %0, %1, %2, %0;" : "+l"(acc) : "l"(a), "l"(b))

// per-block int64-vs-int32 detect (warp 0 ballot -> shared flag).
__device__ __forceinline__ int detect_is64(const void* ei, int* sh) {
    if (threadIdx.x < 32) {
        const long long* p = (const long long*)ei;
        long long v = p[threadIdx.x];
        unsigned m = __ballot_sync(0xffffffffu, v >= 0 && v < N_NODES);
        if (threadIdx.x == 0) *sh = (m == 0xffffffffu);
    }
    __syncthreads();
    return *sh;
}

// ---------------- kernels ----------------
// one fused 64-bit atomic: count + fixed-point weighted in-degree
__global__ void k_prep(const void* __restrict__ eiv,
                       const float* __restrict__ ew, int E) {
    __shared__ int s64;
    int is64 = detect_is64(eiv, &s64);
    int e = blockIdx.x * blockDim.x + threadIdx.x;
    if (e >= E) return;
    int c = is64 ? (int)((const long long*)eiv)[E + e]
                 : ((const int*)eiv)[E + e];
    unsigned long long q = __float2ull_rn(ew[e] * 16777216.0f);
    atomicAdd(&g_hist[c], (1ULL << 40) | q);
}

// block-local exclusive scan of counts + dinv + histogram reset
__global__ void k_scanA() {
    __shared__ int wsum[32];
    int i = blockIdx.x * 1024 + threadIdx.x;
    int lane = threadIdx.x & 31, wid = threadIdx.x >> 5;
    int v = 0;
    if (i < N_NODES) {
        unsigned long long hv = g_hist[i];
        g_hist[i] = 0ULL;   // reset for the next call / replay
        v = (int)(hv >> 40);
        float deg = (float)((double)(hv & DEG_MASK) * (1.0 / 16777216.0));
        g_dinv[i] = rsqrtf(deg + 1.0f);   // +1 = self loop weight
    }
    int incl = v;
#pragma unroll
    for (int d = 1; d < 32; d <<= 1) {
        int t = __shfl_up_sync(0xffffffffu, incl, d);
        if (lane >= d) incl += t;
    }
    if (lane == 31) wsum[wid] = incl;
    __syncthreads();
    if (wid == 0) {
        int s = wsum[lane];
#pragma unroll
        for (int d = 1; d < 32; d <<= 1) {
            int t = __shfl_up_sync(0xffffffffu, s, d);
            if (lane >= d) s += t;
        }
        wsum[lane] = s;
    }
    __syncthreads();
    int woff = (wid > 0) ? wsum[wid - 1] : 0;
    if (i < N_NODES) g_start[i] = incl - v + woff;
    if (threadIdx.x == 1023) g_bsum[blockIdx.x] = wsum[31];
}

// fused: scan of block sums (per-block, warp 0) + apply offsets
__global__ void k_scanC(int E) {
    __shared__ int sh[128];
    int t = threadIdx.x;
    if (t < 128) sh[t] = (t < NBLK_SCAN) ? g_bsum[t] : 0;
    __syncthreads();
    if (t < 32) {
        int e0 = sh[4 * t], e1 = sh[4 * t + 1], e2 = sh[4 * t + 2], e3 = sh[4 * t + 3];
        int s = e0 + e1 + e2 + e3;
        int incl = s;
#pragma unroll
        for (int d = 1; d < 32; d <<= 1) {
            int x = __shfl_up_sync(0xffffffffu, incl, d);
            if (t >= d) incl += x;
        }
        int base = incl - s;
        sh[4 * t] = base;
        sh[4 * t + 1] = base + e0;
        sh[4 * t + 2] = base + e0 + e1;
        sh[4 * t + 3] = base + e0 + e1 + e2;
    }
    __syncthreads();
    int i = blockIdx.x * 1024 + t;
    if (i < N_NODES) {
        int s = g_start[i] + sh[blockIdx.x];
        g_start[i] = s;
        g_pos[i] = s;
    }
    if (i == 0) g_start[N_NODES] = E;
}

// scatter edges into CSR order, packing {row, RAW weight} -- no dinv gathers.
__global__ void k_reorder(const void* __restrict__ eiv,
                          const float* __restrict__ ew, int E) {
    __shared__ int s64;
    int is64 = detect_is64(eiv, &s64);
    int e = blockIdx.x * blockDim.x + threadIdx.x;
    if (e >= E) return;
    int r, c;
    if (is64) {
        const long long* ei = (const long long*)eiv;
        r = (int)ei[e]; c = (int)ei[E + e];
    } else {
        const int* ei = (const int*)eiv;
        r = ei[e]; c = ei[E + e];
    }
    int p = atomicAdd(&g_pos[c], 1);
    g_edge[p] = make_int2(r, __float_as_int(ew[e]));
}

// h1s = (x @ W1) * dinv. Software-pipelined: prefetch chunk c+1 into
// registers (LDG) while computing chunk c from smem; then STS + sync.
// Loads stay in flight across the whole kernel instead of phase-alternating.
__global__ void __launch_bounds__(128) k_gemm1(const float* __restrict__ x,
                                               const float* __restrict__ W1) {
    __shared__ __align__(16) float w1s[F_INN * HID];   // 19200 B
    __shared__ float xs[128 * XS_STR];                 // 16896 B
    int tid = threadIdx.x;
    for (int i = tid; i < F_INN * HID; i += 128) w1s[i] = W1[i];
    int node0 = blockIdx.x * 128;

    // stage chunk 0 (k = 0..31)
#pragma unroll
    for (int j = 0; j < 8; j++) {
        int idx = tid + j * 128;
        int nd = idx >> 3, q = idx & 7;
        float4 v = make_float4(0.f, 0.f, 0.f, 0.f);
        if (node0 + nd < N_NODES)
            v = *(const float4*)&x[(node0 + nd) * F_INN + q * 4];
        float* dst = &xs[nd * XS_STR + q * 4];
        dst[0] = v.x; dst[1] = v.y; dst[2] = v.z; dst[3] = v.w;
    }
    __syncthreads();

    unsigned long long acc[8];
#pragma unroll
    for (int j = 0; j < 8; j++) acc[j] = 0ULL;

    float4 pf[8];
    for (int c = 0; c < NCHUNK; c++) {
        // ---- prefetch next chunk into registers (hidden under compute) ----
        if (c < NCHUNK - 1) {
            int kc = (c + 1) * 32;
#pragma unroll
            for (int j = 0; j < 8; j++) {
                int idx = tid + j * 128;
                int nd = idx >> 3, q = idx & 7;
                pf[j] = make_float4(0.f, 0.f, 0.f, 0.f);
                if (node0 + nd < N_NODES)
                    pf[j] = *(const float4*)&x[(node0 + nd) * F_INN + kc + q * 4];
            }
        } else {
            // tail chunk: 12 floats = 3 float4 per node, 3 per thread
#pragma unroll
            for (int j = 0; j < 3; j++) {
                int idx = tid + j * 128;
                int nd = idx / 3, q = idx - nd * 3;
                pf[j] = make_float4(0.f, 0.f, 0.f, 0.f);
                if (node0 + nd < N_NODES)
                    pf[j] = *(const float4*)&x[(node0 + nd) * F_INN + 288 + q * 4];
            }
        }
        // ---- compute current chunk from smem ----
        int kc = c * 32;
#pragma unroll
        for (int k = 0; k < 32; k++) {
            float xv = xs[tid * XS_STR + k];
            unsigned long long xx;
            asm("mov.b64 %0, {%1, %1};" : "=l"(xx) : "f"(xv));
            const ulonglong2* wr = (const ulonglong2*)&w1s[(kc + k) * HID];
            ulonglong2 w0 = wr[0], w1 = wr[1], w2 = wr[2], w3 = wr[3];
            FFMA2(acc[0], xx, w0.x); FFMA2(acc[1], xx, w0.y);
            FFMA2(acc[2], xx, w1.x); FFMA2(acc[3], xx, w1.y);
            FFMA2(acc[4], xx, w2.x); FFMA2(acc[5], xx, w2.y);
            FFMA2(acc[6], xx, w3.x); FFMA2(acc[7], xx, w3.y);
        }
        __syncthreads();   // all reads of xs done
        // ---- store prefetched chunk to smem ----
        if (c < NCHUNK - 1) {
#pragma unroll
            for (int j = 0; j < 8; j++) {
                int idx = tid + j * 128;
                int nd = idx >> 3, q = idx & 7;
                float* dst = &xs[nd * XS_STR + q * 4];
                dst[0] = pf[j].x; dst[1] = pf[j].y; dst[2] = pf[j].z; dst[3] = pf[j].w;
            }
        } else {
#pragma unroll
            for (int j = 0; j < 3; j++) {
                int idx = tid + j * 128;
                int nd = idx / 3, q = idx - nd * 3;
                float* dst = &xs[nd * XS_STR + q * 4];
                dst[0] = pf[j].x; dst[1] = pf[j].y; dst[2] = pf[j].z; dst[3] = pf[j].w;
            }
        }
        __syncthreads();   // xs ready for next chunk
    }
    // ---- tail compute: k = 288..299 ----
#pragma unroll
    for (int k = 0; k < 12; k++) {
        float xv = xs[tid * XS_STR + k];
        unsigned long long xx;
        asm("mov.b64 %0, {%1, %1};" : "=l"(xx) : "f"(xv));
        const ulonglong2* wr = (const ulonglong2*)&w1s[(288 + k) * HID];
        ulonglong2 w0 = wr[0], w1 = wr[1], w2 = wr[2], w3 = wr[3];
        FFMA2(acc[0], xx, w0.x); FFMA2(acc[1], xx, w0.y);
        FFMA2(acc[2], xx, w1.x); FFMA2(acc[3], xx, w1.y);
        FFMA2(acc[4], xx, w2.x); FFMA2(acc[5], xx, w2.y);
        FFMA2(acc[6], xx, w3.x); FFMA2(acc[7], xx, w3.y);
    }

    int node = node0 + tid;
    if (node < N_NODES) {
        float di = g_dinv[node];
        float o[16];
#pragma unroll
        for (int j = 0; j < 8; j++)
            asm("mov.b64 {%0, %1}, %2;" : "=f"(o[2 * j]), "=f"(o[2 * j + 1]) : "l"(acc[j]));
#pragma unroll
        for (int j = 0; j < 16; j++) o[j] *= di;
        float4* dst = (float4*)&g_h1[node * HID];
        dst[0] = make_float4(o[0], o[1], o[2], o[3]);
        dst[1] = make_float4(o[4], o[5], o[6], o[7]);
        dst[2] = make_float4(o[8], o[9], o[10], o[11]);
        dst[3] = make_float4(o[12], o[13], o[14], o[15]);
    }
}

// conv1 + node1 fused: warp per node gather of w*h1s, then
// v = relu(di*(acc + h1s_self) + b1); h2s = (W2 @ v) * di
__global__ void __launch_bounds__(256) k_conv1(const float* __restrict__ b1,
                                               const float* __restrict__ W2) {
    int warp = (blockIdx.x * blockDim.x + threadIdx.x) >> 5;
    if (warp >= N_NODES) return;
    int lane = threadIdx.x & 31;
    int q = lane & 3, eg = lane >> 2;
    int s = g_start[warp], e = g_start[warp + 1];
    float4 acc = make_float4(0.f, 0.f, 0.f, 0.f);
#pragma unroll 2
    for (int idx = s + eg; idx < e; idx += 8) {
        int2 ed = g_edge[idx];
        float w = __int_as_float(ed.y);
        float4 h = *(const float4*)&g_h1[ed.x * HID + q * 4];
        acc.x += h.x * w; acc.y += h.y * w;
        acc.z += h.z * w; acc.w += h.w * w;
    }
#pragma unroll
    for (int d = 4; d < 32; d <<= 1) {
        acc.x += __shfl_xor_sync(0xffffffffu, acc.x, d);
        acc.y += __shfl_xor_sync(0xffffffffu, acc.y, d);
        acc.z += __shfl_xor_sync(0xffffffffu, acc.z, d);
        acc.w += __shfl_xor_sync(0xffffffffu, acc.w, d);
    }
    float di = g_dinv[warp];
    float4 h1q = *(const float4*)&g_h1[warp * HID + q * 4];   // dinv-scaled
    float4 bq  = *(const float4*)&b1[q * 4];
    float4 v;
    v.x = fmaxf((acc.x + h1q.x) * di + bq.x, 0.f);
    v.y = fmaxf((acc.y + h1q.y) * di + bq.y, 0.f);
    v.z = fmaxf((acc.z + h1q.z) * di + bq.z, 0.f);
    v.w = fmaxf((acc.w + h1q.w) * di + bq.w, 0.f);
    float vv[16];
#pragma unroll
    for (int c = 0; c < 4; c++) {
        vv[4 * c + 0] = __shfl_sync(0xffffffffu, v.x, c);
        vv[4 * c + 1] = __shfl_sync(0xffffffffu, v.y, c);
        vv[4 * c + 2] = __shfl_sync(0xffffffffu, v.z, c);
        vv[4 * c + 3] = __shfl_sync(0xffffffffu, v.w, c);
    }
    if (lane < H2P) {
        float o = 0.f;
        if (lane < C_OUT) {
#pragma unroll
            for (int k = 0; k < HID; k++)
                o += vv[k] * __ldg(&W2[k * C_OUT + lane]);
            o *= di;   // dinv-scaled h2
        }
        g_h2[warp * H2P + lane] = o;
    }
}

// conv2 + final fused: gather w*h2s, t = di*(acc + h2s_self) + b2, log_softmax
__global__ void __launch_bounds__(256) k_conv2(const float* __restrict__ b2,
                                               float* __restrict__ out) {
    int warp = (blockIdx.x * blockDim.x + threadIdx.x) >> 5;
    if (warp >= N_NODES) return;
    int lane = threadIdx.x & 31;
    int q = lane & 3, eg = lane >> 2;
    int s = g_start[warp], e = g_start[warp + 1];
    float4 acc = make_float4(0.f, 0.f, 0.f, 0.f);
#pragma unroll 2
    for (int idx = s + eg; idx < e; idx += 8) {
        int2 ed = g_edge[idx];
        float w = __int_as_float(ed.y);
        if (q < 3) {
            float4 h = *(const float4*)&g_h2[ed.x * H2P + q * 4];
            acc.x += h.x * w; acc.y += h.y * w;
            acc.z += h.z * w; acc.w += h.w * w;
        }
    }
#pragma unroll
    for (int d = 4; d < 32; d <<= 1) {
        acc.x += __shfl_xor_sync(0xffffffffu, acc.x, d);
        acc.y += __shfl_xor_sync(0xffffffffu, acc.y, d);
        acc.z += __shfl_xor_sync(0xffffffffu, acc.z, d);
        acc.w += __shfl_xor_sync(0xffffffffu, acc.w, d);
    }
    float di = g_dinv[warp];
    float4 tq = make_float4(0.f, 0.f, 0.f, 0.f);
    if (q < 3) {
        float4 h2q = *(const float4*)&g_h2[warp * H2P + q * 4];  // dinv-scaled
        tq.x = (acc.x + h2q.x) * di;
        tq.y = (acc.y + h2q.y) * di;
        tq.z = (acc.z + h2q.z) * di;
        tq.w = (acc.w + h2q.w) * di;
    }
    int src = lane >> 2;
    float a0 = __shfl_sync(0xffffffffu, tq.x, src);
    float a1 = __shfl_sync(0xffffffffu, tq.y, src);
    float a2 = __shfl_sync(0xffffffffu, tq.z, src);
    float a3 = __shfl_sync(0xffffffffu, tq.w, src);
    float tj = (q == 0) ? a0 : (q == 1) ? a1 : (q == 2) ? a2 : a3;
    tj = (lane < C_OUT) ? tj + __ldg(&b2[lane]) : -3.4e38f;
    float m = tj;
#pragma unroll
    for (int d = 16; d >= 1; d >>= 1) m = fmaxf(m, __shfl_xor_sync(0xffffffffu, m, d));
    float ex = (lane < C_OUT) ? expf(tj - m) : 0.f;
    float ssum = ex;
#pragma unroll
    for (int d = 16; d >= 1; d >>= 1) ssum += __shfl_xor_sync(0xffffffffu, ssum, d);
    float l = logf(ssum) + m;
    if (lane < C_OUT) out[warp * C_OUT + lane] = tj - l;
}

// ---------------- launcher ----------------
extern "C" void kernel_launch(void* const* d_in, const int* in_sizes, int n_in,
                              void* d_out, int out_size) {
    const float* x  = (const float*)d_in[0];
    const void*  ei = d_in[1];
    const float* ew = (const float*)d_in[2];
    const float* W1 = (const float*)d_in[3];
    const float* b1 = (const float*)d_in[4];
    const float* W2 = (const float*)d_in[5];
    const float* b2 = (const float*)d_in[6];
    float* out = (float*)d_out;
    int E = in_sizes[2];

    k_prep<<<(E + 255) / 256, 256>>>(ei, ew, E);
    k_scanA<<<NBLK_SCAN, 1024>>>();
    k_scanC<<<NBLK_SCAN, 1024>>>(E);
    k_reorder<<<(E + 255) / 256, 256>>>(ei, ew, E);
    k_gemm1<<<(N_NODES + 127) / 128, 128>>>(x, W1);
    k_conv1<<<(N_NODES * 32 + 255) / 256, 256>>>(b1, W2);
    k_conv2<<<(N_NODES * 32 + 255) / 256, 256>>>(b2, out);
}